// round 13
// baseline (speedup 1.0000x reference)
#include <cuda_runtime.h>
#include <limits.h>
#include <stdint.h>

typedef unsigned long long u64;

// Problem constants
#define BATCH 32
#define NPTS  131072            // 2^17
#define BN    (BATCH*NPTS)      // 4194304
#define TSEL  32768
#define CELL  0.05f

// Batch-partitioned hash: batch b owns slots [b<<18, (b+1)<<18)
// Entries are COMPLEMENT-encoded: entry = ~((key<<32)|minIdx); EMPTY = 0
#define LBITS 18
#define LMASK ((1u<<LBITS)-1)
#define HSIZE (BATCH<<LBITS)     // 2^23 total slots, 64MB

// Scan config: 1024 blocks x 4096 elements (256 thr x 16)
#define NBLK  1024
#define CHUNK 4096
#define SCANT 256
#define ITEMS 16

// Lookback state flags
#define FLAG1 (1ull << 62)
#define FLAG2 (2ull << 62)
#define SFMASK (3ull << 62)
#define PUBBIT (1ull << 63)
#define VALMASK 0x3FFFFFFFull

// Output layout (flattened, concatenated, all f32)
#define OFF_Y    0
#define OFF_IDX  (BATCH*TSEL*3)
#define OFF_MASK (OFF_IDX + BATCH*TSEL*2)
#define OFF_UL   (OFF_MASK + BATCH*TSEL)
#define OFF_ULI  (OFF_UL + BN)

// Tail grid
#define TAILBLK (NBLK + BATCH + 64)

// Scratch (static zero-init == EMPTY for the complement-encoded hash)
__device__ u64 d_h[HSIZE];
__device__ unsigned d_slot[BN];        // slot idx; after k_fused: fi
__device__ u64 d_state[NBLK];
__device__ u64 d_bbase[BATCH+1];
__device__ unsigned d_ticket;

__device__ __forceinline__ int quant(float v) {
    return (int)rintf(__fdiv_rn(v, CELL));
}
__device__ __forceinline__ unsigned mkkey(int b, int q0, int q1, int q2) {
    return ((unsigned)b << 27) | ((unsigned)(q0 + 256) << 18)
         | ((unsigned)(q1 + 256) << 9) | (unsigned)(q2 + 256);
}
__device__ __forceinline__ unsigned khash18(unsigned k) {
    return (k * 2654435761u) >> (32 - LBITS);
}

// ---------------------------------------------------------------------------
// K1: insert — 4 points/thread, batched independent CAS (MLP=4)
//     Block 0 additionally clears the small lookback state for this replay.
__global__ void k_insert(const float* __restrict__ x) {
    int j = blockIdx.x * blockDim.x + threadIdx.x;   // [0, BN/4)
    if (blockIdx.x == 0) {
        for (int s = threadIdx.x; s < NBLK; s += blockDim.x) d_state[s] = 0;
        if (threadIdx.x <= BATCH) d_bbase[threadIdx.x] = 0;
        if (threadIdx.x == 0) d_ticket = 0;
    }
    int i0 = 4 * j;
    int b  = i0 >> 17;                               // 4 points share batch
    unsigned base = (unsigned)b << LBITS;

    // 3 x LDG.128 = 12 floats = 4 points
    const float4* xv = (const float4*)(x + 3 * i0);
    float4 fa = __ldcs(&xv[0]);
    float4 fb = __ldcs(&xv[1]);
    float4 fc = __ldcs(&xv[2]);
    float px[12] = {fa.x,fa.y,fa.z,fa.w, fb.x,fb.y,fb.z,fb.w, fc.x,fc.y,fc.z,fc.w};

    unsigned key[4], hl[4];
    u64 enc[4];
    #pragma unroll
    for (int e = 0; e < 4; e++) {
        int q0 = quant(px[3*e+0]);
        int q1 = quant(px[3*e+1]);
        int q2 = quant(px[3*e+2]);
        key[e] = mkkey(b, q0, q1, q2);
        hl[e]  = khash18(key[e]);
        enc[e] = ~(((u64)key[e] << 32) | (unsigned)(i0 + e));
    }

    // issue all 4 first-probe CASes back-to-back (independent chains)
    u64 old4[4];
    #pragma unroll
    for (int e = 0; e < 4; e++)
        old4[e] = atomicCAS(&d_h[base | hl[e]], 0ull, enc[e]);

    // resolve each (rarely loops: load factor <= 0.5)
    unsigned slot[4];
    #pragma unroll
    for (int e = 0; e < 4; e++) {
        unsigned h = base | hl[e];
        u64 old = old4[e];
        while (true) {
            if (old == 0ull) break;                  // claimed
            u64 dec = ~old;
            if ((unsigned)(dec >> 32) == key[e]) {
                if ((unsigned)dec > (unsigned)(i0 + e))
                    atomicMax(&d_h[h], enc[e]);      // min idx == max encoded
                break;
            }
            hl[e] = (hl[e] + 1) & LMASK;
            h = base | hl[e];
            old = atomicCAS(&d_h[h], 0ull, enc[e]);
        }
        slot[e] = h;
    }
    __stcs((uint4*)(d_slot + i0), make_uint4(slot[0], slot[1], slot[2], slot[3]));
}

// ---------------------------------------------------------------------------
// K2: fused flags + decoupled-lookback scan + scatters
__global__ void __launch_bounds__(SCANT) k_fused(float* __restrict__ out) {
    __shared__ int s_tb;
    __shared__ int wsum[8];
    __shared__ int wexc[8];
    __shared__ int s_total;
    __shared__ unsigned s_excl, s_pb;

    int t = threadIdx.x;
    if (t == 0) s_tb = (int)atomicAdd(&d_ticket, 1u);
    __syncthreads();
    int tb = s_tb;
    int i0 = tb * CHUNK + t * ITEMS;

    unsigned ss[ITEMS];
    #pragma unroll
    for (int v = 0; v < 4; v++) {
        uint4 sv = *(const uint4*)(d_slot + i0 + 4*v);
        ss[4*v+0] = sv.x; ss[4*v+1] = sv.y; ss[4*v+2] = sv.z; ss[4*v+3] = sv.w;
    }

    // entry read (decode with one NOT): low -> fi, high -> key
    unsigned hk[ITEMS];
    unsigned fi[ITEMS];
    unsigned fmask = 0;
    int pre[ITEMS];
    int c = 0;
    #pragma unroll
    for (int e = 0; e < ITEMS; e++) {
        u64 dec = ~__ldcg(&d_h[ss[e]]);
        fi[e] = (unsigned)dec;
        hk[e] = (unsigned)(dec >> 32);
        unsigned f = (fi[e] == (unsigned)(i0 + e));
        fmask |= f << e;
        pre[e] = c;
        c += (int)f;
    }

    // block scan of per-thread counts
    int lane = t & 31, wid = t >> 5;
    int inc = c;
    #pragma unroll
    for (int o = 1; o < 32; o <<= 1) {
        int u = __shfl_up_sync(0xFFFFFFFFu, inc, o);
        if (lane >= o) inc += u;
    }
    if (lane == 31) wsum[wid] = inc;
    __syncthreads();
    if (t < 8) {
        int val = wsum[t];
        int ic = val;
        #pragma unroll
        for (int o = 1; o < 8; o <<= 1) {
            int u = __shfl_up_sync(0xFFu, ic, o);
            if (t >= o) ic += u;
        }
        wexc[t] = ic - val;
        if (t == 7) s_total = ic;
    }
    __syncthreads();
    int agg = s_total;

    // decoupled lookback (thread 0)
    if (t == 0) {
        unsigned excl = 0;
        if (tb == 0) {
            __threadfence();
            atomicExch(&d_state[0], FLAG2 | (u64)agg);
        } else {
            atomicExch(&d_state[tb], FLAG1 | (u64)agg);
            int j = tb - 1;
            while (true) {
                u64 s = *(volatile u64*)&d_state[j];
                u64 f = s & SFMASK;
                if (f == 0) continue;
                excl += (unsigned)(s & VALMASK);
                if (f == FLAG2) break;
                j--;
            }
            __threadfence();
            atomicExch(&d_state[tb], FLAG2 | (u64)(excl + (unsigned)agg));
        }
        int m = tb >> 5;
        unsigned pbv;
        if ((tb & 31) == 0) {
            __threadfence();
            atomicExch(&d_bbase[m], PUBBIT | (u64)excl);
            pbv = excl;
        } else {
            while (true) {
                u64 s = *(volatile u64*)&d_bbase[m];
                if (s & PUBBIT) { pbv = (unsigned)(s & VALMASK); break; }
            }
        }
        if (tb == NBLK - 1) {
            __threadfence();
            atomicExch(&d_bbase[BATCH], PUBBIT | (u64)(excl + (unsigned)agg));
        }
        s_excl = excl;
        s_pb = pbv;
    }
    __syncthreads();

    int thOff = (int)s_excl + wexc[wid] + (inc - c);
    int pb = (int)s_pb;
    int b = tb >> 5;

    // overwrite d_slot with fi (firsts: fi == i) — coalesced uint4
    #pragma unroll
    for (int v = 0; v < 4; v++) {
        uint4 o4 = make_uint4(fi[4*v+0], fi[4*v+1], fi[4*v+2], fi[4*v+3]);
        __stcs((uint4*)(d_slot + i0 + 4*v), o4);
    }

    // scatter: firsts — UL (own index, mostly-dense), ULI, selected y/idx/mask
    #pragma unroll
    for (int e = 0; e < ITEMS; e++) {
        if ((fmask >> e) & 1) {
            int i  = i0 + e;
            int p  = thOff + pre[e];
            out[OFF_UL + i] = (float)p;
            __stcs(&out[OFF_ULI + p], (float)i);
            int r = p - pb;
            if (r < TSEL) {
                unsigned key = hk[e];
                int il = i & (NPTS - 1);
                float y0 = CELL * (float)((int)((key >> 18) & 511) - 256);
                float y1 = CELL * (float)((int)((key >> 9) & 511) - 256);
                float y2 = CELL * (float)((int)(key & 511) - 256);
                int o = b * TSEL + r;
                __stcs(&out[OFF_Y + 3*o + 0], y0);
                __stcs(&out[OFF_Y + 3*o + 1], y1);
                __stcs(&out[OFF_Y + 3*o + 2], y2);
                __stcs(&out[OFF_IDX + 2*o + 0], (float)b);
                __stcs(&out[OFF_IDX + 2*o + 1], (float)il);
                __stcs(&out[OFF_MASK + o], 1.0f);
            }
        }
    }
}

// ---------------------------------------------------------------------------
// K3: combined tail — UL gather + fixup + SENT tail, then hash pre-clear
__global__ void k_tail(const float* __restrict__ x, float* __restrict__ out) {
    int blk = blockIdx.x;
    int t = threadIdx.x;

    if (blk < NBLK) {
        // ul_idx for ALL points, branch-free: UL[i] = UL[fi]
        int i0 = blk * CHUNK + t * ITEMS;
        unsigned f[ITEMS];
        #pragma unroll
        for (int v = 0; v < 4; v++) {
            uint4 f4 = *(const uint4*)(d_slot + i0 + 4*v);
            f[4*v+0] = f4.x; f[4*v+1] = f4.y; f[4*v+2] = f4.z; f[4*v+3] = f4.w;
        }
        float r[ITEMS];
        #pragma unroll
        for (int e = 0; e < ITEMS; e++)
            r[e] = __ldcg(&out[OFF_UL + f[e]]);
        #pragma unroll
        for (int v = 0; v < 4; v++) {
            float4 r4 = make_float4(r[4*v+0], r[4*v+1], r[4*v+2], r[4*v+3]);
            __stcs((float4*)(out + OFF_UL + i0 + 4*v), r4);
        }
    } else {
        int fb = blk - NBLK;
        if (fb >= BATCH) {
            // ULI SENT tail
            int U = (int)(d_bbase[BATCH] & VALMASK);
            int nb = 64;
            for (int i = U + (fb - BATCH) * blockDim.x + t; i < BN; i += nb * blockDim.x)
                __stcs(&out[OFF_ULI + i], (float)BN);
        } else {
            int pb0 = (int)(d_bbase[fb] & VALMASK);
            int pb1 = (int)(d_bbase[fb + 1] & VALMASK);
            int Kb = pb1 - pb0;
            if (Kb < TSEL) {
                // Dormant slow path (d_slot holds fi: first <=> fi == i)
                __shared__ int s_run;
                __shared__ int cw[8];
                if (t == 0) s_run = 0;
                __syncthreads();
                for (int base = 0; base < NPTS; base += SCANT) {
                    int il = base + t;
                    int i = fb * NPTS + il;
                    int isf = (d_slot[i] == (unsigned)i);
                    int lane = t & 31, wid = t >> 5;
                    int incv = isf;
                    #pragma unroll
                    for (int o = 1; o < 32; o <<= 1) {
                        int u = __shfl_up_sync(0xFFFFFFFFu, incv, o);
                        if (lane >= o) incv += u;
                    }
                    if (lane == 31) cw[wid] = incv;
                    __syncthreads();
                    int woff = 0;
                    for (int k = 0; k < wid; k++) woff += cw[k];
                    int r = s_run + woff + incv - isf;
                    if (!isf) {
                        int tt = Kb + (il - r);
                        if (tt < TSEL) {
                            float y0 = CELL * rintf(__fdiv_rn(__ldg(&x[3*i+0]), CELL));
                            float y1 = CELL * rintf(__fdiv_rn(__ldg(&x[3*i+1]), CELL));
                            float y2 = CELL * rintf(__fdiv_rn(__ldg(&x[3*i+2]), CELL));
                            int o = fb * TSEL + tt;
                            out[OFF_Y + 3*o + 0] = y0;
                            out[OFF_Y + 3*o + 1] = y1;
                            out[OFF_Y + 3*o + 2] = y2;
                            out[OFF_IDX + 2*o + 0] = (float)fb;
                            out[OFF_IDX + 2*o + 1] = (float)il;
                            out[OFF_MASK + o] = 0.0f;
                        }
                    }
                    __syncthreads();
                    if (t == 0) {
                        int tot = 0;
                        #pragma unroll
                        for (int k = 0; k < 8; k++) tot += cw[k];
                        s_run += tot;
                    }
                    __syncthreads();
                }
            }
        }
    }

    // hash pre-clear for the next replay (EMPTY = 0), all blocks participate
    {
        ulonglong2* p = (ulonglong2*)d_h;
        const unsigned n = HSIZE / 2;
        unsigned stride = (unsigned)TAILBLK * SCANT;
        for (unsigned j = (unsigned)blk * SCANT + t; j < n; j += stride)
            __stcs(&p[j], make_ulonglong2(0ull, 0ull));
    }
}

// ---------------------------------------------------------------------------
extern "C" void kernel_launch(void* const* d_in, const int* in_sizes, int n_in,
                              void* d_out, int out_size) {
    const float* x = (const float*)d_in[0];
    float* out = (float*)d_out;
    (void)in_sizes; (void)n_in; (void)out_size;

    k_insert<<<BN / 4 / 256, 256>>>(x);
    k_fused <<<NBLK, SCANT>>>(out);
    k_tail  <<<TAILBLK, SCANT>>>(x, out);
}

// round 15
// speedup vs baseline: 1.1400x; 1.1400x over previous
#include <cuda_runtime.h>
#include <limits.h>
#include <stdint.h>

typedef unsigned long long u64;

// Problem constants
#define BATCH 32
#define NPTS  131072            // 2^17
#define BN    (BATCH*NPTS)      // 4194304
#define TSEL  32768
#define CELL  0.05f

// Batch-partitioned hash: batch b owns slots [b<<18, (b+1)<<18)
// Entries are COMPLEMENT-encoded: entry = ~((key<<32)|minIdx); EMPTY = 0
#define LBITS 18
#define LMASK ((1u<<LBITS)-1)
#define HSIZE (BATCH<<LBITS)     // 2^23 total slots, 64MB

// Scan config: 1024 blocks x 4096 elements (256 thr x 16)
#define NBLK  1024
#define CHUNK 4096
#define SCANT 256
#define ITEMS 16

// Lookback state flags
#define FLAG1 (1ull << 62)       // aggregate available
#define FLAG2 (2ull << 62)       // inclusive available
#define SFMASK (3ull << 62)
#define PUBBIT (1ull << 63)
#define VALMASK 0x3FFFFFFFull

// Output layout (flattened, concatenated, all f32)
#define OFF_Y    0
#define OFF_IDX  (BATCH*TSEL*3)
#define OFF_MASK (OFF_IDX + BATCH*TSEL*2)
#define OFF_UL   (OFF_MASK + BATCH*TSEL)
#define OFF_ULI  (OFF_UL + BN)

// Tail grid
#define TAILBLK (NBLK + BATCH + 64)

// Scratch (static zero-init == EMPTY for the complement-encoded hash)
__device__ u64 d_h[HSIZE];
__device__ unsigned d_slot[BN];        // slot idx; after k_fused: fi
__device__ u64 d_state[NBLK];
__device__ u64 d_bbase[BATCH+1];
__device__ unsigned d_ticket;

__device__ __forceinline__ int quant(float v) {
    return (int)rintf(__fdiv_rn(v, CELL));
}
__device__ __forceinline__ unsigned mkkey(int b, int q0, int q1, int q2) {
    return ((unsigned)b << 27) | ((unsigned)(q0 + 256) << 18)
         | ((unsigned)(q1 + 256) << 9) | (unsigned)(q2 + 256);
}
__device__ __forceinline__ unsigned khash18(unsigned k) {
    return (k * 2654435761u) >> (32 - LBITS);
}

// ---------------------------------------------------------------------------
// K1: insert, CAS-first probing, 1 point/thread (max TLP, low regs).
//     Block 0 additionally clears the small lookback state for this replay.
__global__ void k_insert(const float* __restrict__ x) {
    int i = blockIdx.x * blockDim.x + threadIdx.x;   // [0, BN)
    if (blockIdx.x == 0) {
        for (int j = threadIdx.x; j < NBLK; j += blockDim.x) d_state[j] = 0;
        if (threadIdx.x <= BATCH) d_bbase[threadIdx.x] = 0;
        if (threadIdx.x == 0) d_ticket = 0;
    }
    float x0 = __ldcs(&x[3*i+0]);
    float x1 = __ldcs(&x[3*i+1]);
    float x2 = __ldcs(&x[3*i+2]);
    int q0 = quant(x0), q1 = quant(x1), q2 = quant(x2);
    int b = i >> 17;
    unsigned key = mkkey(b, q0, q1, q2);
    u64 enc = ~(((u64)key << 32) | (unsigned)i);     // complement encoding
    unsigned base = (unsigned)b << LBITS;
    unsigned hl = khash18(key);
    while (true) {
        unsigned h = base | hl;
        u64 old = atomicCAS(&d_h[h], 0ull, enc);
        if (old == 0ull) { __stcs(&d_slot[i], h); break; }
        u64 dec = ~old;
        if ((unsigned)(dec >> 32) == key) {
            if ((unsigned)dec > (unsigned)i)
                atomicMax(&d_h[h], enc);             // min idx == max encoded
            __stcs(&d_slot[i], h);
            break;
        }
        hl = (hl + 1) & LMASK;
    }
}

// ---------------------------------------------------------------------------
// K2: fused flags + WARP-PARALLEL decoupled-lookback scan + scatters
__global__ void __launch_bounds__(SCANT) k_fused(float* __restrict__ out) {
    __shared__ int s_tb;
    __shared__ int wsum[8];
    __shared__ int wexc[8];
    __shared__ int s_total;
    __shared__ unsigned s_excl, s_pb;

    int t = threadIdx.x;
    if (t == 0) s_tb = (int)atomicAdd(&d_ticket, 1u);
    __syncthreads();
    int tb = s_tb;
    int i0 = tb * CHUNK + t * ITEMS;

    unsigned ss[ITEMS];
    #pragma unroll
    for (int v = 0; v < 4; v++) {
        uint4 sv = *(const uint4*)(d_slot + i0 + 4*v);
        ss[4*v+0] = sv.x; ss[4*v+1] = sv.y; ss[4*v+2] = sv.z; ss[4*v+3] = sv.w;
    }

    // entry read (decode with one NOT): low -> fi, high -> key
    unsigned hk[ITEMS];
    unsigned fi[ITEMS];
    unsigned fmask = 0;
    int pre[ITEMS];
    int c = 0;
    #pragma unroll
    for (int e = 0; e < ITEMS; e++) {
        u64 dec = ~__ldcg(&d_h[ss[e]]);
        fi[e] = (unsigned)dec;
        hk[e] = (unsigned)(dec >> 32);
        unsigned f = (fi[e] == (unsigned)(i0 + e));
        fmask |= f << e;
        pre[e] = c;
        c += (int)f;
    }

    // block scan of per-thread counts
    int lane = t & 31, wid = t >> 5;
    int inc = c;
    #pragma unroll
    for (int o = 1; o < 32; o <<= 1) {
        int u = __shfl_up_sync(0xFFFFFFFFu, inc, o);
        if (lane >= o) inc += u;
    }
    if (lane == 31) wsum[wid] = inc;
    __syncthreads();
    if (t < 8) {
        int val = wsum[t];
        int ic = val;
        #pragma unroll
        for (int o = 1; o < 8; o <<= 1) {
            int u = __shfl_up_sync(0xFFu, ic, o);
            if (t >= o) ic += u;
        }
        wexc[t] = ic - val;
        if (t == 7) s_total = ic;
    }
    __syncthreads();
    int agg = s_total;

    // WARP-PARALLEL decoupled lookback (warp 0)
    if (t < 32) {
        unsigned excl = 0;
        if (tb == 0) {
            if (t == 0) {
                __threadfence();
                atomicExch(&d_state[0], FLAG2 | (u64)agg);
            }
        } else {
            if (t == 0) atomicExch(&d_state[tb], FLAG1 | (u64)agg);
            int wbase = tb;                      // window covers [wbase-32, wbase)
            while (true) {
                int j = wbase - 32 + t;          // lane t reads state j
                u64 s;
                if (j >= 0) {
                    s = *(volatile u64*)&d_state[j];
                    while ((s & SFMASK) == 0)    // wait until published
                        s = *(volatile u64*)&d_state[j];
                } else {
                    s = FLAG2;                   // virtual inclusive 0 before start
                }
                unsigned incm = __ballot_sync(0xFFFFFFFFu, (s & SFMASK) == FLAG2);
                if (incm) {
                    int hi = 31 - __clz(incm);   // highest lane holding an inclusive
                    unsigned contrib = (t >= hi) ? (unsigned)(s & VALMASK) : 0u;
                    #pragma unroll
                    for (int o = 16; o; o >>= 1)
                        contrib += __shfl_xor_sync(0xFFFFFFFFu, contrib, o);
                    excl += contrib;
                    break;
                } else {
                    unsigned contrib = (unsigned)(s & VALMASK);
                    #pragma unroll
                    for (int o = 16; o; o >>= 1)
                        contrib += __shfl_xor_sync(0xFFFFFFFFu, contrib, o);
                    excl += contrib;
                    wbase -= 32;
                }
            }
            if (t == 0) {
                __threadfence();
                atomicExch(&d_state[tb], FLAG2 | (u64)(excl + (unsigned)agg));
            }
        }
        if (t == 0) {
            int m = tb >> 5;
            unsigned pbv;
            if ((tb & 31) == 0) {
                __threadfence();
                atomicExch(&d_bbase[m], PUBBIT | (u64)excl);
                pbv = excl;
            } else {
                while (true) {
                    u64 s = *(volatile u64*)&d_bbase[m];
                    if (s & PUBBIT) { pbv = (unsigned)(s & VALMASK); break; }
                }
            }
            if (tb == NBLK - 1) {
                __threadfence();
                atomicExch(&d_bbase[BATCH], PUBBIT | (u64)(excl + (unsigned)agg));
            }
            s_excl = excl;
            s_pb = pbv;
        }
    }
    __syncthreads();

    int thOff = (int)s_excl + wexc[wid] + (inc - c);
    int pb = (int)s_pb;
    int b = tb >> 5;

    // overwrite d_slot with fi (firsts: fi == i) — coalesced uint4
    #pragma unroll
    for (int v = 0; v < 4; v++) {
        uint4 o4 = make_uint4(fi[4*v+0], fi[4*v+1], fi[4*v+2], fi[4*v+3]);
        __stcs((uint4*)(d_slot + i0 + 4*v), o4);
    }

    // scatter: firsts — UL (own index, mostly-dense), ULI, selected y/idx/mask
    #pragma unroll
    for (int e = 0; e < ITEMS; e++) {
        if ((fmask >> e) & 1) {
            int i  = i0 + e;
            int p  = thOff + pre[e];
            out[OFF_UL + i] = (float)p;
            __stcs(&out[OFF_ULI + p], (float)i);
            int r = p - pb;
            if (r < TSEL) {
                unsigned key = hk[e];
                int il = i & (NPTS - 1);
                float y0 = CELL * (float)((int)((key >> 18) & 511) - 256);
                float y1 = CELL * (float)((int)((key >> 9) & 511) - 256);
                float y2 = CELL * (float)((int)(key & 511) - 256);
                int o = b * TSEL + r;
                __stcs(&out[OFF_Y + 3*o + 0], y0);
                __stcs(&out[OFF_Y + 3*o + 1], y1);
                __stcs(&out[OFF_Y + 3*o + 2], y2);
                __stcs(&out[OFF_IDX + 2*o + 0], (float)b);
                __stcs(&out[OFF_IDX + 2*o + 1], (float)il);
                __stcs(&out[OFF_MASK + o], 1.0f);
            }
        }
    }
}

// ---------------------------------------------------------------------------
// K3: combined tail — UL gather + fixup + SENT tail, then hash pre-clear
__global__ void k_tail(const float* __restrict__ x, float* __restrict__ out) {
    int blk = blockIdx.x;
    int t = threadIdx.x;

    if (blk < NBLK) {
        // ul_idx for ALL points, branch-free: UL[i] = UL[fi]
        int i0 = blk * CHUNK + t * ITEMS;
        unsigned f[ITEMS];
        #pragma unroll
        for (int v = 0; v < 4; v++) {
            uint4 f4 = *(const uint4*)(d_slot + i0 + 4*v);
            f[4*v+0] = f4.x; f[4*v+1] = f4.y; f[4*v+2] = f4.z; f[4*v+3] = f4.w;
        }
        float r[ITEMS];
        #pragma unroll
        for (int e = 0; e < ITEMS; e++)
            r[e] = __ldcg(&out[OFF_UL + f[e]]);
        #pragma unroll
        for (int v = 0; v < 4; v++) {
            float4 r4 = make_float4(r[4*v+0], r[4*v+1], r[4*v+2], r[4*v+3]);
            __stcs((float4*)(out + OFF_UL + i0 + 4*v), r4);
        }
    } else {
        int fb = blk - NBLK;
        if (fb >= BATCH) {
            // ULI SENT tail
            int U = (int)(d_bbase[BATCH] & VALMASK);
            int nb = 64;
            for (int i = U + (fb - BATCH) * blockDim.x + t; i < BN; i += nb * blockDim.x)
                __stcs(&out[OFF_ULI + i], (float)BN);
        } else {
            int pb0 = (int)(d_bbase[fb] & VALMASK);
            int pb1 = (int)(d_bbase[fb + 1] & VALMASK);
            int Kb = pb1 - pb0;
            if (Kb < TSEL) {
                // Dormant slow path (d_slot holds fi: first <=> fi == i)
                __shared__ int s_run;
                __shared__ int cw[8];
                if (t == 0) s_run = 0;
                __syncthreads();
                for (int base = 0; base < NPTS; base += SCANT) {
                    int il = base + t;
                    int i = fb * NPTS + il;
                    int isf = (d_slot[i] == (unsigned)i);
                    int lane = t & 31, wid = t >> 5;
                    int incv = isf;
                    #pragma unroll
                    for (int o = 1; o < 32; o <<= 1) {
                        int u = __shfl_up_sync(0xFFFFFFFFu, incv, o);
                        if (lane >= o) incv += u;
                    }
                    if (lane == 31) cw[wid] = incv;
                    __syncthreads();
                    int woff = 0;
                    for (int k = 0; k < wid; k++) woff += cw[k];
                    int r = s_run + woff + incv - isf;
                    if (!isf) {
                        int tt = Kb + (il - r);
                        if (tt < TSEL) {
                            float y0 = CELL * rintf(__fdiv_rn(__ldg(&x[3*i+0]), CELL));
                            float y1 = CELL * rintf(__fdiv_rn(__ldg(&x[3*i+1]), CELL));
                            float y2 = CELL * rintf(__fdiv_rn(__ldg(&x[3*i+2]), CELL));
                            int o = fb * TSEL + tt;
                            out[OFF_Y + 3*o + 0] = y0;
                            out[OFF_Y + 3*o + 1] = y1;
                            out[OFF_Y + 3*o + 2] = y2;
                            out[OFF_IDX + 2*o + 0] = (float)fb;
                            out[OFF_IDX + 2*o + 1] = (float)il;
                            out[OFF_MASK + o] = 0.0f;
                        }
                    }
                    __syncthreads();
                    if (t == 0) {
                        int tot = 0;
                        #pragma unroll
                        for (int k = 0; k < 8; k++) tot += cw[k];
                        s_run += tot;
                    }
                    __syncthreads();
                }
            }
        }
    }

    // hash pre-clear for the next replay (EMPTY = 0), all blocks participate
    {
        ulonglong2* p = (ulonglong2*)d_h;
        const unsigned n = HSIZE / 2;
        unsigned stride = (unsigned)TAILBLK * SCANT;
        for (unsigned j = (unsigned)blk * SCANT + t; j < n; j += stride)
            __stcs(&p[j], make_ulonglong2(0ull, 0ull));
    }
}

// ---------------------------------------------------------------------------
extern "C" void kernel_launch(void* const* d_in, const int* in_sizes, int n_in,
                              void* d_out, int out_size) {
    const float* x = (const float*)d_in[0];
    float* out = (float*)d_out;
    (void)in_sizes; (void)n_in; (void)out_size;

    k_insert<<<BN / 256, 256>>>(x);
    k_fused <<<NBLK, SCANT>>>(out);
    k_tail  <<<TAILBLK, SCANT>>>(x, out);
}